// round 15
// baseline (speedup 1.0000x reference)
#include <cuda_runtime.h>
#include <cuda_bf16.h>
#include <stdint.h>
#include <math.h>

// Problem constants
#define NB   2
#define HH   8
#define TT   1024
#define HID  64
#define NHB  (NB*HH)
#define D2   (2*HID)
#define EMB  (HH*HID)          // 512
#define LCH  64
#define NCH  (TT/LCH)          // 16
#define CTX_ELEMS (NB*HH*TT*HID)
#define ANG_K 0.0015339807878856412f

typedef unsigned long long u64t;

__device__ __forceinline__ uint32_t smem_u32(const void* p) {
    uint32_t a;
    asm("{ .reg .u64 t; cvta.to.shared.u64 t, %1; cvt.u32.u64 %0, t; }" : "=r"(a) : "l"(p));
    return a;
}

// ---- warp MMA + cp.async helpers (verified R8-R14) ----
__device__ __forceinline__ void ldsm_x4(uint32_t& r0, uint32_t& r1, uint32_t& r2, uint32_t& r3,
                                        uint32_t addr) {
    asm volatile("ldmatrix.sync.aligned.m8n8.x4.shared.b16 {%0,%1,%2,%3}, [%4];"
                 : "=r"(r0), "=r"(r1), "=r"(r2), "=r"(r3) : "r"(addr));
}
__device__ __forceinline__ void mma_bf16(float* c, const uint32_t* a, const uint32_t* b) {
    asm volatile("mma.sync.aligned.m16n8k16.row.col.f32.bf16.bf16.f32 "
                 "{%0,%1,%2,%3}, {%4,%5,%6,%7}, {%8,%9}, {%0,%1,%2,%3};"
                 : "+f"(c[0]), "+f"(c[1]), "+f"(c[2]), "+f"(c[3])
                 : "r"(a[0]), "r"(a[1]), "r"(a[2]), "r"(a[3]), "r"(b[0]), "r"(b[1]));
}
__device__ __forceinline__ void cp16(uint32_t dst, const void* src) {
    asm volatile("cp.async.ca.shared.global [%0], [%1], 16;" :: "r"(dst), "l"(src));
}
#define CP_COMMIT()  asm volatile("cp.async.commit_group;" ::: "memory")
#define CP_WAIT(n)   asm volatile("cp.async.wait_group %0;" :: "n"(n) : "memory")

__device__ __forceinline__ void split4(float4 x, uint32_t& h0, uint32_t& h1,
                                       uint32_t& l0, uint32_t& l1) {
    __nv_bfloat16 a = __float2bfloat16(x.x), b = __float2bfloat16(x.y),
                  c = __float2bfloat16(x.z), d = __float2bfloat16(x.w);
    __nv_bfloat162 hA(a, b), hB(c, d);
    h0 = *reinterpret_cast<uint32_t*>(&hA);
    h1 = *reinterpret_cast<uint32_t*>(&hB);
    __nv_bfloat162 lA(__float2bfloat16(x.x - __bfloat162float(a)),
                      __float2bfloat16(x.y - __bfloat162float(b)));
    __nv_bfloat162 lB(__float2bfloat16(x.z - __bfloat162float(c)),
                      __float2bfloat16(x.w - __bfloat162float(d)));
    l0 = *reinterpret_cast<uint32_t*>(&lA);
    l1 = *reinterpret_cast<uint32_t*>(&lB);
}
__device__ __forceinline__ void split2(float v0, float v1, uint32_t& hp, uint32_t& lp) {
    __nv_bfloat16 h0 = __float2bfloat16(v0), h1 = __float2bfloat16(v1);
    __nv_bfloat162 hv(h0, h1);
    hp = *reinterpret_cast<uint32_t*>(&hv);
    __nv_bfloat162 lv(__float2bfloat16(v0 - __bfloat162float(h0)),
                      __float2bfloat16(v1 - __bfloat162float(h1)));
    lp = *reinterpret_cast<uint32_t*>(&lv);
}
__device__ __forceinline__ void splitS(float v, __nv_bfloat16& h, __nv_bfloat16& l) {
    h = __float2bfloat16(v);
    l = __float2bfloat16(v - __bfloat162float(h));
}

// Scratch (device globals)
__device__ __align__(16) __nv_bfloat16 g_PTH[NHB*NCH*2*64*64];
__device__ __align__(16) __nv_bfloat16 g_PTL[NHB*NCH*2*64*64];
__device__ float g_skP [NHB*NCH*D2];
__device__ __align__(16) __nv_bfloat16 g_attnH[TT*NB*EMB];
__device__ __align__(16) __nv_bfloat16 g_attnL[TT*NB*EMB];
__device__ __align__(16) __nv_bfloat16 g_WH[EMB*EMB];
__device__ __align__(16) __nv_bfloat16 g_WL[EMB*EMB];

// ---------------------------------------------------------------------------
// Kernel A v2: fused chunk-sums + exclusive prefix + skP + W-split
// grid (16, 13):
//   y in [0,8)  : P slice block (b = x, m-slice = y): running prefix in regs
//   y == 8      : skP scan for b = x
//   y in [9,13) : W split (64 blocks)
// ---------------------------------------------------------------------------
__global__ __launch_bounds__(256) void sums_prefix_kernel(const float* __restrict__ k,
                                                          const float* __restrict__ v,
                                                          const float* __restrict__ W) {
    __shared__ float sm[6656];   // wS[1024] wC[1024] sK[4096] sV[512]
    float* wS = sm;
    float* wC = sm + 1024;
    float* sK = sm + 2048;
    float* sV = sm + 6144;

    const int tid = threadIdx.x;
    const int b = blockIdx.x;
    const int y = blockIdx.y;

    if (y >= 9) {
        // ---- W split (64 blocks) ----
        const int blk = b + (y - 9) * 16;
        const int gt = blk * 256 + tid;
        const float4* W4 = reinterpret_cast<const float4*>(W);
#pragma unroll
        for (int j = 0; j < 4; ++j) {
            int idx = j * 16384 + gt;
            float4 x = W4[idx];
            uint32_t h0, h1, l0, l1;
            split4(x, h0, h1, l0, l1);
            *reinterpret_cast<uint2*>(&g_WH[idx * 4]) = make_uint2(h0, h1);
            *reinterpret_cast<uint2*>(&g_WL[idx * 4]) = make_uint2(l0, l1);
        }
        return;
    }

    // weight tables (full T)
    for (int i = tid; i < TT; i += 256) {
        float ang = (float)(i + 1) * ANG_K;
        wS[i] = sinf(ang);
        wC[i] = cosf(ang);
    }
    __syncthreads();

    if (y == 8) {
        // ---- skP scan: thread = expanded d (0..127) ----
        if (tid < D2) {
            const int dr = tid & 63;
            const float* wT = (tid < 64) ? wS : wC;
            const float* kb = k + (size_t)b * TT * HID;
            float run = 0.f;
            for (int c = 0; c < NCH; ++c) {
                g_skP[(b * NCH + c) * D2 + tid] = run;
#pragma unroll 8
                for (int t = 0; t < LCH; ++t) {
                    int tg = c * LCH + t;
                    run += wT[tg] * fmaxf(kb[(size_t)tg * HID + dr], 0.f);
                }
            }
        }
        return;
    }

    // ---- P slice block: m in [y*8, y*8+8) ----
    const int ms = y;
    const int m_local = tid >> 5;        // warp id 0..7 = m within slice
    const int dx = tid & 31;
    const int half = dx >> 4;            // 0 = sin, 1 = cos
    const int dr = (dx & 15) * 4;        // raw d base
    const float* wT = half ? wC : wS;

    float acc[4] = {0.f, 0.f, 0.f, 0.f};     // running exclusive prefix (fp32)
    const float4* kg = reinterpret_cast<const float4*>(k + (size_t)b * TT * HID);
    const int m_global = ms * 8 + m_local;

    for (int c = 0; c < NCH; ++c) {
        // store current prefix as P_c (exclusive)
        {
            uint32_t h0, l0, h1, l1;
            split2(acc[0], acc[1], h0, l0);
            split2(acc[2], acc[3], h1, l1);
            size_t off = ((size_t)((b * NCH + c) * 2 + half)) * 4096
                       + (size_t)m_global * 64 + dr;
            *reinterpret_cast<uint2*>(&g_PTH[off]) = make_uint2(h0, h1);
            *reinterpret_cast<uint2*>(&g_PTL[off]) = make_uint2(l0, l1);
        }
        // stage chunk c: relu K [64t][64d], V slice [64t][8m]
        for (int i = tid; i < 1024; i += 256) {
            int t = i >> 4, c4 = i & 15;
            float4 kv = kg[(size_t)(c * LCH + t) * 16 + c4];
            reinterpret_cast<float4*>(sK)[t * 16 + c4] =
                make_float4(fmaxf(kv.x, 0.f), fmaxf(kv.y, 0.f),
                            fmaxf(kv.z, 0.f), fmaxf(kv.w, 0.f));
        }
        for (int i = tid; i < 512; i += 256) {
            int t = i >> 3, m = i & 7;
            sV[i] = v[((size_t)(c * LCH + t) * NHB + b) * HID + ms * 8 + m];
        }
        __syncthreads();
        // accumulate S_c into running prefix
        const float4* sK4 = reinterpret_cast<const float4*>(sK);
#pragma unroll 4
        for (int t = 0; t < LCH; ++t) {
            float wv = wT[c * LCH + t] * sV[t * 8 + m_local];
            float4 kk = sK4[t * 16 + (dr >> 2)];
            acc[0] = fmaf(kk.x, wv, acc[0]);
            acc[1] = fmaf(kk.y, wv, acc[1]);
            acc[2] = fmaf(kk.z, wv, acc[2]);
            acc[3] = fmaf(kk.w, wv, acc[3]);
        }
        __syncthreads();
    }
}

// ---------------------------------------------------------------------------
// Kernel C v4: chunk output (byte-identical to R14, passing)
// ---------------------------------------------------------------------------
#define ROW2 144
#define CW_QH  0
#define CW_QL  9216
#define CW_SH  18432
#define CW_SL  27648
#define CW_VH  36864
#define CW_VL  46080
#define CW_P0H 55296
#define CW_P0L 64512
#define CW_P1H 73728
#define CW_P1L 82944
#define CW_FLT 92160
#define SM_CO  (CW_FLT + 1792)

__global__ __launch_bounds__(256, 2) void chunk_out_hmma(const float* __restrict__ q,
                                                         const float* __restrict__ k,
                                                         const float* __restrict__ v) {
    extern __shared__ char smc[];
    const uint32_t sbase = smem_u32(smc);
    const int tid = threadIdx.x;
    const int wid = tid >> 5, lane = tid & 31;
    const int wm = wid & 3, wn = wid >> 2;
    const int b = blockIdx.x, c = blockIdx.y;

    float* sF = reinterpret_cast<float*>(smc + CW_FLT);
    if (tid < 64) {
        float ang = (float)(c * LCH + tid + 1) * ANG_K;
        sF[tid] = sinf(ang);
        sF[64 + tid] = cosf(ang);
    }
    if (tid < 128) sF[128 + tid] = g_skP[(b * NCH + c) * D2 + tid];

    const float4* qg = reinterpret_cast<const float4*>(q + ((size_t)b * TT + c * LCH) * HID);
    const float4* kg = reinterpret_cast<const float4*>(k + ((size_t)b * TT + c * LCH) * HID);
    for (int i = tid; i < 1024; i += 256) {
        int t = i >> 4, c4 = i & 15;
        float4 qv = qg[i];
        qv = make_float4(fmaxf(qv.x, 0.f), fmaxf(qv.y, 0.f), fmaxf(qv.z, 0.f), fmaxf(qv.w, 0.f));
        uint32_t h0, h1, l0, l1;
        split4(qv, h0, h1, l0, l1);
        *reinterpret_cast<uint2*>(smc + CW_QH + t * ROW2 + c4 * 8) = make_uint2(h0, h1);
        *reinterpret_cast<uint2*>(smc + CW_QL + t * ROW2 + c4 * 8) = make_uint2(l0, l1);
        float4 kv = kg[i];
        kv = make_float4(fmaxf(kv.x, 0.f), fmaxf(kv.y, 0.f), fmaxf(kv.z, 0.f), fmaxf(kv.w, 0.f));
        split4(kv, h0, h1, l0, l1);
        *reinterpret_cast<uint2*>(smc + CW_SH + t * ROW2 + c4 * 8) = make_uint2(h0, h1);
        *reinterpret_cast<uint2*>(smc + CW_SL + t * ROW2 + c4 * 8) = make_uint2(l0, l1);
    }
    {
        const float4* vg = reinterpret_cast<const float4*>(v);
        __nv_bfloat16* vh = reinterpret_cast<__nv_bfloat16*>(smc + CW_VH);
        __nv_bfloat16* vl = reinterpret_cast<__nv_bfloat16*>(smc + CW_VL);
        for (int i = tid; i < 1024; i += 256) {
            int tp = i >> 4, mq = i & 15;
            float4 x = vg[((size_t)(c * LCH + tp) * NHB + b) * 16 + mq];
            float xv[4] = {x.x, x.y, x.z, x.w};
#pragma unroll
            for (int e = 0; e < 4; ++e) {
                __nv_bfloat16 h, l;
                splitS(xv[e], h, l);
                vh[(4 * mq + e) * 72 + tp] = h;
                vl[(4 * mq + e) * 72 + tp] = l;
            }
        }
    }
    {
        const size_t basePT = ((size_t)((b * NCH + c) * 2)) * 4096;
        for (int i = tid; i < 1024; i += 256) {
            int half = i >> 9;
            int j = i & 511;
            int row = j >> 3, g = j & 7;
            size_t off = basePT + (size_t)half * 4096 + (size_t)row * 64 + g * 8;
            int dsth = half ? CW_P1H : CW_P0H;
            int dstl = half ? CW_P1L : CW_P0L;
            *reinterpret_cast<uint4*>(smc + dsth + row * ROW2 + g * 16) =
                *reinterpret_cast<const uint4*>(&g_PTH[off]);
            *reinterpret_cast<uint4*>(smc + dstl + row * ROW2 + g * 16) =
                *reinterpret_cast<const uint4*>(&g_PTL[off]);
        }
    }
    __syncthreads();

    const uint32_t aOffQ = (uint32_t)((wm * 16 + (lane & 15)) * ROW2 + ((lane >> 4) * 8) * 2);
    const uint32_t bOffB = (uint32_t)(((lane & 7) + ((lane >> 4) << 3)) * ROW2 +
                                      (((lane >> 3) & 1) * 8) * 2);

    float acc[4][4];
#pragma unroll
    for (int j = 0; j < 4; ++j)
#pragma unroll
        for (int e = 0; e < 4; ++e) acc[j][e] = 0.f;
    for (int ks = 0; ks < 4; ++ks) {
        const int ko = ks * 32;
        uint32_t ah[4], al[4];
        ldsm_x4(ah[0], ah[1], ah[2], ah[3], sbase + CW_QH + aOffQ + ko);
        ldsm_x4(al[0], al[1], al[2], al[3], sbase + CW_QL + aOffQ + ko);
#pragma unroll
        for (int pl = 0; pl < 2; ++pl) {
            const int p = wn * 2 + pl;
            if (p > wm) continue;
            uint32_t bh[4], bl[4];
            ldsm_x4(bh[0], bh[1], bh[2], bh[3], sbase + CW_SH + bOffB + p * 16 * ROW2 + ko);
            ldsm_x4(bl[0], bl[1], bl[2], bl[3], sbase + CW_SL + bOffB + p * 16 * ROW2 + ko);
            mma_bf16(acc[2*pl],   ah, bh);     mma_bf16(acc[2*pl],   ah, bl);
            mma_bf16(acc[2*pl],   al, bh);
            mma_bf16(acc[2*pl+1], ah, bh + 2); mma_bf16(acc[2*pl+1], ah, bl + 2);
            mma_bf16(acc[2*pl+1], al, bh + 2);
        }
    }

    const int gr = lane >> 2, gc = (lane & 3) * 2;
    const int r0 = wm * 16 + gr, r1 = r0 + 8;
    const float sr0 = sF[r0], cr0 = sF[64 + r0];
    const float sr1 = sF[r1], cr1 = sF[64 + r1];
    float rs0 = 0.f, rs1 = 0.f;
#pragma unroll
    for (int j = 0; j < 4; ++j) {
        int c0 = wn * 32 + j * 8 + gc, c1 = c0 + 1;
        float sc0 = sF[c0], cc0 = sF[64 + c0], sc1 = sF[c1], cc1 = sF[64 + c1];
        acc[j][0] = (c0 <= r0) ? acc[j][0] * (cr0 * cc0 + sr0 * sc0) : 0.f;
        acc[j][1] = (c1 <= r0) ? acc[j][1] * (cr0 * cc1 + sr0 * sc1) : 0.f;
        acc[j][2] = (c0 <= r1) ? acc[j][2] * (cr1 * cc0 + sr1 * sc0) : 0.f;
        acc[j][3] = (c1 <= r1) ? acc[j][3] * (cr1 * cc1 + sr1 * sc1) : 0.f;
        rs0 += acc[j][0] + acc[j][1];
        rs1 += acc[j][2] + acc[j][3];
    }
    rs0 += __shfl_xor_sync(0xFFFFFFFFu, rs0, 1); rs0 += __shfl_xor_sync(0xFFFFFFFFu, rs0, 2);
    rs1 += __shfl_xor_sync(0xFFFFFFFFu, rs1, 1); rs1 += __shfl_xor_sync(0xFFFFFFFFu, rs1, 2);
    if ((lane & 3) == 0) {
        sF[256 + wn * 64 + r0] = rs0;
        sF[256 + wn * 64 + r1] = rs1;
    }
    __syncthreads();

#pragma unroll
    for (int j = 0; j < 4; ++j) {
        int col = wn * 32 + j * 8 + gc;
        uint32_t hp, lp;
        split2(acc[j][0], acc[j][1], hp, lp);
        *reinterpret_cast<uint32_t*>(smc + CW_SH + r0 * ROW2 + col * 2) = hp;
        *reinterpret_cast<uint32_t*>(smc + CW_SL + r0 * ROW2 + col * 2) = lp;
        split2(acc[j][2], acc[j][3], hp, lp);
        *reinterpret_cast<uint32_t*>(smc + CW_SH + r1 * ROW2 + col * 2) = hp;
        *reinterpret_cast<uint32_t*>(smc + CW_SL + r1 * ROW2 + col * 2) = lp;
    }
    if (wn == 0) {
        float qd0 = 0.f, qd1 = 0.f;
        const __nv_bfloat16* qh = reinterpret_cast<const __nv_bfloat16*>(smc + CW_QH);
        const __nv_bfloat16* ql = reinterpret_cast<const __nv_bfloat16*>(smc + CW_QL);
        const int d0 = (lane & 3) * 16;
#pragma unroll
        for (int j = 0; j < 16; ++j) {
            int dl = d0 + j;
            float w0 = sr0 * sF[128 + dl] + cr0 * sF[192 + dl];
            float w1 = sr1 * sF[128 + dl] + cr1 * sF[192 + dl];
            float q0 = __bfloat162float(qh[r0 * 72 + dl]) + __bfloat162float(ql[r0 * 72 + dl]);
            float q1 = __bfloat162float(qh[r1 * 72 + dl]) + __bfloat162float(ql[r1 * 72 + dl]);
            qd0 += q0 * w0;
            qd1 += q1 * w1;
        }
        qd0 += __shfl_xor_sync(0xFFFFFFFFu, qd0, 1); qd0 += __shfl_xor_sync(0xFFFFFFFFu, qd0, 2);
        qd1 += __shfl_xor_sync(0xFFFFFFFFu, qd1, 1); qd1 += __shfl_xor_sync(0xFFFFFFFFu, qd1, 2);
        if ((lane & 3) == 0) {
            sF[384 + r0] = fmaxf(sF[256 + r0] + sF[320 + r0] + qd0, 1e-6f);
            sF[384 + r1] = fmaxf(sF[256 + r1] + sF[320 + r1] + qd1, 1e-6f);
        }
    }
    __syncthreads();

    float accO[4][4];
#pragma unroll
    for (int j = 0; j < 4; ++j)
#pragma unroll
        for (int e = 0; e < 4; ++e) accO[j][e] = 0.f;
    for (int ks = 0; ks < 4; ++ks) {
        const int ko = ks * 32;
        uint32_t ah[4], al[4];
        ldsm_x4(ah[0], ah[1], ah[2], ah[3], sbase + CW_SH + aOffQ + ko);
        ldsm_x4(al[0], al[1], al[2], al[3], sbase + CW_SL + aOffQ + ko);
#pragma unroll
        for (int pl = 0; pl < 2; ++pl) {
            const int p = wn * 2 + pl;
            uint32_t bh[4], bl[4];
            ldsm_x4(bh[0], bh[1], bh[2], bh[3], sbase + CW_VH + bOffB + p * 16 * ROW2 + ko);
            ldsm_x4(bl[0], bl[1], bl[2], bl[3], sbase + CW_VL + bOffB + p * 16 * ROW2 + ko);
            mma_bf16(accO[2*pl],   ah, bh);     mma_bf16(accO[2*pl],   ah, bl);
            mma_bf16(accO[2*pl],   al, bh);
            mma_bf16(accO[2*pl+1], ah, bh + 2); mma_bf16(accO[2*pl+1], ah, bl + 2);
            mma_bf16(accO[2*pl+1], al, bh + 2);
        }
    }
#pragma unroll
    for (int half = 0; half < 2; ++half) {
        const int ph = half ? CW_P1H : CW_P0H;
        const int plo = half ? CW_P1L : CW_P0L;
        float accT[4][4];
#pragma unroll
        for (int j = 0; j < 4; ++j)
#pragma unroll
            for (int e = 0; e < 4; ++e) accT[j][e] = 0.f;
        for (int ks = 0; ks < 4; ++ks) {
            const int ko = ks * 32;
            uint32_t ah[4], al[4];
            ldsm_x4(ah[0], ah[1], ah[2], ah[3], sbase + CW_QH + aOffQ + ko);
            ldsm_x4(al[0], al[1], al[2], al[3], sbase + CW_QL + aOffQ + ko);
#pragma unroll
            for (int pl = 0; pl < 2; ++pl) {
                const int p = wn * 2 + pl;
                uint32_t bh[4], bl[4];
                ldsm_x4(bh[0], bh[1], bh[2], bh[3], sbase + ph  + bOffB + p * 16 * ROW2 + ko);
                ldsm_x4(bl[0], bl[1], bl[2], bl[3], sbase + plo + bOffB + p * 16 * ROW2 + ko);
                mma_bf16(accT[2*pl],   ah, bh);     mma_bf16(accT[2*pl],   ah, bl);
                mma_bf16(accT[2*pl],   al, bh);
                mma_bf16(accT[2*pl+1], ah, bh + 2); mma_bf16(accT[2*pl+1], ah, bl + 2);
                mma_bf16(accT[2*pl+1], al, bh + 2);
            }
        }
        const float w0 = half ? cr0 : sr0;
        const float w1 = half ? cr1 : sr1;
#pragma unroll
        for (int j = 0; j < 4; ++j) {
            accO[j][0] += w0 * accT[j][0];
            accO[j][1] += w0 * accT[j][1];
            accO[j][2] += w1 * accT[j][2];
            accO[j][3] += w1 * accT[j][3];
        }
    }

    const float inv0 = 1.0f / sF[384 + r0], inv1 = 1.0f / sF[384 + r1];
    const int n = b >> 3, hh = b & 7;
    const size_t base0 = ((size_t)(c * LCH + r0) * NB + n) * EMB + hh * HID;
    const size_t base1 = ((size_t)(c * LCH + r1) * NB + n) * EMB + hh * HID;
#pragma unroll
    for (int j = 0; j < 4; ++j) {
        int col = wn * 32 + j * 8 + gc;
        uint32_t hp, lp;
        split2(accO[j][0] * inv0, accO[j][1] * inv0, hp, lp);
        *reinterpret_cast<uint32_t*>(&g_attnH[base0 + col]) = hp;
        *reinterpret_cast<uint32_t*>(&g_attnL[base0 + col]) = lp;
        split2(accO[j][2] * inv1, accO[j][3] * inv1, hp, lp);
        *reinterpret_cast<uint32_t*>(&g_attnH[base1 + col]) = hp;
        *reinterpret_cast<uint32_t*>(&g_attnL[base1 + col]) = lp;
    }
}

// ---------------------------------------------------------------------------
// Kernel D v7: outproj (byte-identical to R14, passing)
// ---------------------------------------------------------------------------
#define ROWB2 144
#define BUF_BYTES (4 * 64 * ROWB2)
#define OAH2 0
#define OAL2 (64 * ROWB2)
#define OBH2 (2 * 64 * ROWB2)
#define OBL2 (3 * 64 * ROWB2)
#define SM_HMMA (2 * BUF_BYTES)

__global__ __launch_bounds__(256, 2) void outproj_hmma_kernel(const float* __restrict__ bias,
                                                              float* __restrict__ out) {
    extern __shared__ char smc[];
    const uint32_t sbase = smem_u32(smc);
    const int tid = threadIdx.x;
    const int wid = tid >> 5, lane = tid & 31;
    const int wm = wid & 3, wn = wid >> 2;
    const int rb = blockIdx.x * 64;
    const int nb = blockIdx.y * 64;

    float acc[4][4];
#pragma unroll
    for (int nt = 0; nt < 4; ++nt)
#pragma unroll
        for (int e = 0; e < 4; ++e) acc[nt][e] = 0.f;

    auto stage = [&](int kc, int bufIdx) {
        const uint32_t bufs = sbase + bufIdx * BUF_BYTES;
        const size_t kbase = (size_t)kc * 64;
#pragma unroll
        for (int j = 0; j < 8; ++j) {
            int i = tid + j * 256;
            int arr = i >> 9;
            int jj = i & 511;
            int row = jj >> 3, g = jj & 7;
            const __nv_bfloat16* srcp;
            uint32_t dst;
            if (arr == 0) {
                srcp = &g_attnH[(size_t)(rb + row) * EMB + kbase + g * 8];
                dst = bufs + OAH2 + row * ROWB2 + g * 16;
            } else if (arr == 1) {
                srcp = &g_attnL[(size_t)(rb + row) * EMB + kbase + g * 8];
                dst = bufs + OAL2 + row * ROWB2 + g * 16;
            } else if (arr == 2) {
                srcp = &g_WH[(size_t)(nb + row) * EMB + kbase + g * 8];
                dst = bufs + OBH2 + row * ROWB2 + g * 16;
            } else {
                srcp = &g_WL[(size_t)(nb + row) * EMB + kbase + g * 8];
                dst = bufs + OBL2 + row * ROWB2 + g * 16;
            }
            cp16(dst, srcp);
        }
        CP_COMMIT();
    };

    const uint32_t aOff = (uint32_t)((wm * 16 + (lane & 15)) * ROWB2 + ((lane >> 4) * 8) * 2);
    const uint32_t bOff = (uint32_t)((wn * 32 + (lane & 7) + ((lane >> 4) << 3)) * ROWB2 +
                                     (((lane >> 3) & 1) * 8) * 2);

    stage(0, 0);
    for (int kc = 0; kc < 8; ++kc) {
        if (kc < 7) stage(kc + 1, (kc + 1) & 1);
        if (kc < 7) { CP_WAIT(1); } else { CP_WAIT(0); }
        __syncthreads();

        const uint32_t bufs = sbase + (kc & 1) * BUF_BYTES;
#pragma unroll
        for (int ks = 0; ks < 4; ++ks) {
            const int ko = ks * 32;
            uint32_t ah[4], al[4];
            ldsm_x4(ah[0], ah[1], ah[2], ah[3], bufs + OAH2 + aOff + ko);
            ldsm_x4(al[0], al[1], al[2], al[3], bufs + OAL2 + aOff + ko);
            uint32_t bh[4][2], bl[4][2];
#pragma unroll
            for (int p = 0; p < 2; ++p) {
                ldsm_x4(bh[2*p][0], bh[2*p][1], bh[2*p+1][0], bh[2*p+1][1],
                        bufs + OBH2 + bOff + p * 16 * ROWB2 + ko);
                ldsm_x4(bl[2*p][0], bl[2*p][1], bl[2*p+1][0], bl[2*p+1][1],
                        bufs + OBL2 + bOff + p * 16 * ROWB2 + ko);
            }
#pragma unroll
            for (int nt = 0; nt < 4; ++nt) {
                mma_bf16(acc[nt], ah, bh[nt]);
                mma_bf16(acc[nt], ah, bl[nt]);
                mma_bf16(acc[nt], al, bh[nt]);
            }
        }
        __syncthreads();
    }

    const int gr = lane >> 2, gc = (lane & 3) * 2;
    const int h = blockIdx.y;
#pragma unroll
    for (int nt = 0; nt < 4; ++nt) {
        int d = wn * 32 + nt * 8 + gc;
        float b0 = bias[nb + d], b1 = bias[nb + d + 1];
#pragma unroll
        for (int half = 0; half < 2; ++half) {
            int r = rb + wm * 16 + gr + half * 8;
            int t = r >> 1, n = r & 1;
            size_t oidx = (((size_t)(n * HH + h) * TT) + t) * HID + d;
            *reinterpret_cast<float2*>(out + oidx) =
                make_float2(acc[nt][half * 2 + 0] + b0,
                            acc[nt][half * 2 + 1] + b1);
        }
    }
}

// ---------------------------------------------------------------------------
// Launch
// ---------------------------------------------------------------------------
extern "C" void kernel_launch(void* const* d_in, const int* in_sizes, int n_in,
                              void* d_out, int out_size) {
    const float* q    = (const float*)d_in[0];
    const float* k    = (const float*)d_in[1];
    const float* v    = (const float*)d_in[2];
    const float* W    = (const float*)d_in[3];
    const float* bias = (const float*)d_in[4];
    float* out = (float*)d_out;

    static cudaStream_t s_side = nullptr;
    static cudaEvent_t evF = nullptr, evJ = nullptr;
    if (!s_side) {
        cudaStreamCreateWithFlags(&s_side, cudaStreamNonBlocking);
        cudaEventCreateWithFlags(&evF, cudaEventDisableTiming);
        cudaEventCreateWithFlags(&evJ, cudaEventDisableTiming);
    }

    cudaFuncSetAttribute(chunk_out_hmma,
                         cudaFuncAttributeMaxDynamicSharedMemorySize, SM_CO);
    cudaFuncSetAttribute(outproj_hmma_kernel,
                         cudaFuncAttributeMaxDynamicSharedMemorySize, SM_HMMA);

    const bool has_probs = (out_size > CTX_ELEMS);
    if (has_probs) {
        cudaEventRecord(evF, 0);
        cudaStreamWaitEvent(s_side, evF, 0);
        cudaMemsetAsync(out + CTX_ELEMS, 0,
                        (size_t)(out_size - CTX_ELEMS) * sizeof(float), s_side);
        cudaEventRecord(evJ, s_side);
    }

    sums_prefix_kernel<<<dim3(NHB, 13), 256>>>(k, v, W);
    chunk_out_hmma<<<dim3(NHB, NCH), 256, SM_CO>>>(q, k, v);
    outproj_hmma_kernel<<<dim3(32, 8), 256, SM_HMMA>>>(bias, out);

    if (has_probs) cudaStreamWaitEvent(0, evJ, 0);
}

// round 16
// speedup vs baseline: 3.6152x; 3.6152x over previous
#include <cuda_runtime.h>
#include <cuda_bf16.h>
#include <stdint.h>
#include <math.h>

// Problem constants
#define NB   2
#define HH   8
#define TT   1024
#define HID  64
#define NHB  (NB*HH)
#define D2   (2*HID)
#define EMB  (HH*HID)          // 512
#define LCH  64
#define NCH  (TT/LCH)          // 16
#define CTX_ELEMS (NB*HH*TT*HID)
#define ANG_K 0.0015339807878856412f

typedef unsigned long long u64t;

__device__ __forceinline__ u64t pack2(float lo, float hi) {
    u64t r; asm("mov.b64 %0, {%1, %2};" : "=l"(r) : "f"(lo), "f"(hi)); return r;
}
__device__ __forceinline__ float2 unpack2(u64t p) {
    float2 r; asm("mov.b64 {%0, %1}, %2;" : "=f"(r.x), "=f"(r.y) : "l"(p)); return r;
}
__device__ __forceinline__ void fma2(u64t& d, u64t a, u64t b) {
    asm("fma.rn.f32x2 %0, %1, %2, %0;" : "+l"(d) : "l"(a), "l"(b));
}
__device__ __forceinline__ void mul2(u64t& d, u64t a, u64t b) {
    asm("mul.rn.f32x2 %0, %1, %2;" : "=l"(d) : "l"(a), "l"(b));
}
__device__ __forceinline__ uint32_t smem_u32(const void* p) {
    uint32_t a;
    asm("{ .reg .u64 t; cvta.to.shared.u64 t, %1; cvt.u32.u64 %0, t; }" : "=r"(a) : "l"(p));
    return a;
}

// ---- warp MMA + cp.async helpers (verified R8-R14) ----
__device__ __forceinline__ void ldsm_x4(uint32_t& r0, uint32_t& r1, uint32_t& r2, uint32_t& r3,
                                        uint32_t addr) {
    asm volatile("ldmatrix.sync.aligned.m8n8.x4.shared.b16 {%0,%1,%2,%3}, [%4];"
                 : "=r"(r0), "=r"(r1), "=r"(r2), "=r"(r3) : "r"(addr));
}
__device__ __forceinline__ void mma_bf16(float* c, const uint32_t* a, const uint32_t* b) {
    asm volatile("mma.sync.aligned.m16n8k16.row.col.f32.bf16.bf16.f32 "
                 "{%0,%1,%2,%3}, {%4,%5,%6,%7}, {%8,%9}, {%0,%1,%2,%3};"
                 : "+f"(c[0]), "+f"(c[1]), "+f"(c[2]), "+f"(c[3])
                 : "r"(a[0]), "r"(a[1]), "r"(a[2]), "r"(a[3]), "r"(b[0]), "r"(b[1]));
}
__device__ __forceinline__ void cp16(uint32_t dst, const void* src) {
    asm volatile("cp.async.ca.shared.global [%0], [%1], 16;" :: "r"(dst), "l"(src));
}
#define CP_COMMIT()  asm volatile("cp.async.commit_group;" ::: "memory")
#define CP_WAIT(n)   asm volatile("cp.async.wait_group %0;" :: "n"(n) : "memory")

__device__ __forceinline__ void split4(float4 x, uint32_t& h0, uint32_t& h1,
                                       uint32_t& l0, uint32_t& l1) {
    __nv_bfloat16 a = __float2bfloat16(x.x), b = __float2bfloat16(x.y),
                  c = __float2bfloat16(x.z), d = __float2bfloat16(x.w);
    __nv_bfloat162 hA(a, b), hB(c, d);
    h0 = *reinterpret_cast<uint32_t*>(&hA);
    h1 = *reinterpret_cast<uint32_t*>(&hB);
    __nv_bfloat162 lA(__float2bfloat16(x.x - __bfloat162float(a)),
                      __float2bfloat16(x.y - __bfloat162float(b)));
    __nv_bfloat162 lB(__float2bfloat16(x.z - __bfloat162float(c)),
                      __float2bfloat16(x.w - __bfloat162float(d)));
    l0 = *reinterpret_cast<uint32_t*>(&lA);
    l1 = *reinterpret_cast<uint32_t*>(&lB);
}
__device__ __forceinline__ void split2(float v0, float v1, uint32_t& hp, uint32_t& lp) {
    __nv_bfloat16 h0 = __float2bfloat16(v0), h1 = __float2bfloat16(v1);
    __nv_bfloat162 hv(h0, h1);
    hp = *reinterpret_cast<uint32_t*>(&hv);
    __nv_bfloat162 lv(__float2bfloat16(v0 - __bfloat162float(h0)),
                      __float2bfloat16(v1 - __bfloat162float(h1)));
    lp = *reinterpret_cast<uint32_t*>(&lv);
}
__device__ __forceinline__ void splitS(float v, __nv_bfloat16& h, __nv_bfloat16& l) {
    h = __float2bfloat16(v);
    l = __float2bfloat16(v - __bfloat162float(h));
}

// Scratch (device globals)
__device__ __align__(16) __nv_bfloat16 g_STH[NHB*NCH*2*64*64];
__device__ __align__(16) __nv_bfloat16 g_STL[NHB*NCH*2*64*64];
__device__ __align__(16) __nv_bfloat16 g_PTH[NHB*NCH*2*64*64];
__device__ __align__(16) __nv_bfloat16 g_PTL[NHB*NCH*2*64*64];
__device__ float g_sk  [NHB*NCH*D2];
__device__ float g_skP [NHB*NCH*D2];
__device__ __align__(16) __nv_bfloat16 g_attnH[TT*NB*EMB];
__device__ __align__(16) __nv_bfloat16 g_attnL[TT*NB*EMB];
__device__ __align__(16) __nv_bfloat16 g_WH[EMB*EMB];
__device__ __align__(16) __nv_bfloat16 g_WL[EMB*EMB];

// ---------------------------------------------------------------------------
// Kernel A+W fused (R14 version, passing)
// ---------------------------------------------------------------------------
__global__ __launch_bounds__(256) void chunk_sums_kernel(const float* __restrict__ k,
                                                         const float* __restrict__ v,
                                                         const float* __restrict__ W) {
    extern __shared__ float sm[];
    const int tid = threadIdx.x;

    if (blockIdx.y >= NCH) {
        const int blk = blockIdx.x + (blockIdx.y - NCH) * 16;
        const int gt = blk * 256 + tid;
        const float4* W4 = reinterpret_cast<const float4*>(W);
#pragma unroll
        for (int j = 0; j < 4; ++j) {
            int idx = j * 16384 + gt;
            float4 x = W4[idx];
            uint32_t h0, h1, l0, l1;
            split4(x, h0, h1, l0, l1);
            *reinterpret_cast<uint2*>(&g_WH[idx * 4]) = make_uint2(h0, h1);
            *reinterpret_cast<uint2*>(&g_WL[idx * 4]) = make_uint2(l0, l1);
        }
        return;
    }

    float* sK   = sm;
    float* sV   = sm + 4096;
    float* sSin = sm + 8192;
    float* sCos = sm + 8256;
    const int b = blockIdx.x, c = blockIdx.y;

    if (tid < LCH) {
        float ang = (float)(c * LCH + tid + 1) * ANG_K;
        sSin[tid] = sinf(ang);
        sCos[tid] = cosf(ang);
    }
    const float4* kg = reinterpret_cast<const float4*>(k + ((size_t)b * TT + c * LCH) * HID);
    float4* sK4w = reinterpret_cast<float4*>(sK);
    for (int i = tid; i < LCH * 16; i += 256) {
        float4 kv = kg[i];
        sK4w[i] = make_float4(fmaxf(kv.x, 0.f), fmaxf(kv.y, 0.f),
                              fmaxf(kv.z, 0.f), fmaxf(kv.w, 0.f));
    }
    const float4* vg = reinterpret_cast<const float4*>(v);
    float4* sV4w = reinterpret_cast<float4*>(sV);
    for (int i = tid; i < LCH * 16; i += 256) {
        int t = i >> 4, c4 = i & 15;
        sV4w[t * 16 + c4] = vg[((size_t)(c * LCH + t) * NHB + b) * 16 + c4];
    }
    __syncthreads();

    const int tx = tid & 15, ty = tid >> 4;
    const int m0 = tx * 4;
    const float* wT = (ty < 8) ? sSin : sCos;
    u64t acc[8][2];
#pragma unroll
    for (int i = 0; i < 8; ++i) { acc[i][0] = pack2(0.f, 0.f); acc[i][1] = pack2(0.f, 0.f); }

    const float4* sK4 = reinterpret_cast<const float4*>(sK);
    const float4* sV4 = reinterpret_cast<const float4*>(sV);
    for (int t = 0; t < LCH; ++t) {
        float4 a0 = sK4[t * 16 + (ty & 7) * 2];
        float4 a1 = sK4[t * 16 + (ty & 7) * 2 + 1];
        float4 bv = sV4[t * 16 + tx];
        float w = wT[t];
        u64t wp = pack2(w, w);
        u64t b01 = pack2(bv.x, bv.y), b23 = pack2(bv.z, bv.w);
        mul2(b01, b01, wp);
        mul2(b23, b23, wp);
        float av[8] = {a0.x, a0.y, a0.z, a0.w, a1.x, a1.y, a1.z, a1.w};
#pragma unroll
        for (int i = 0; i < 8; ++i) {
            u64t ad = pack2(av[i], av[i]);
            fma2(acc[i][0], ad, b01);
            fma2(acc[i][1], ad, b23);
        }
    }

    const int half = ty >> 3;
    const int draw = (ty & 7) * 8;
    const size_t base = ((size_t)((b * NCH + c) * 2 + half)) * 4096;
#pragma unroll
    for (int j = 0; j < 4; ++j) {
        float vals[8];
#pragma unroll
        for (int i = 0; i < 8; ++i) {
            float2 pp = unpack2(acc[i][j >> 1]);
            vals[i] = (j & 1) ? pp.y : pp.x;
        }
        uint32_t hw[4], lw[4];
#pragma unroll
        for (int g = 0; g < 4; ++g) {
            uint32_t hp, lp;
            split2(vals[2 * g], vals[2 * g + 1], hp, lp);
            hw[g] = hp; lw[g] = lp;
        }
        size_t off = base + (size_t)(m0 + j) * 64 + draw;
        *reinterpret_cast<uint4*>(&g_STH[off]) = make_uint4(hw[0], hw[1], hw[2], hw[3]);
        *reinterpret_cast<uint4*>(&g_STL[off]) = make_uint4(lw[0], lw[1], lw[2], lw[3]);
    }

    if (tid < D2) {
        int dl = tid & 63;
        const float* wv = (tid < 64) ? sSin : sCos;
        float s = 0.f;
        for (int t = 0; t < LCH; ++t) s += wv[t] * sK[t * HID + dl];
        g_sk[(b * NCH + c) * D2 + tid] = s;
    }
}

// ---------------------------------------------------------------------------
// Kernel B: exclusive prefix (R14 version, passing)
// ---------------------------------------------------------------------------
__global__ __launch_bounds__(256) void prefix_kernel() {
    const int b = blockIdx.x, s = blockIdx.y, tid = threadIdx.x;
    const int e = s * 256 + tid;
    float r0 = 0.f, r1 = 0.f;
#pragma unroll
    for (int c = 0; c < NCH; ++c) {
        size_t idx = ((size_t)(b * NCH + c)) * 8192 + (size_t)e * 2;
        uint32_t hp, lp;
        split2(r0, r1, hp, lp);
        *reinterpret_cast<uint32_t*>(&g_PTH[idx]) = hp;
        *reinterpret_cast<uint32_t*>(&g_PTL[idx]) = lp;
        uint32_t hs = *reinterpret_cast<const uint32_t*>(&g_STH[idx]);
        uint32_t ls = *reinterpret_cast<const uint32_t*>(&g_STL[idx]);
        __nv_bfloat162 h2 = *reinterpret_cast<__nv_bfloat162*>(&hs);
        __nv_bfloat162 l2 = *reinterpret_cast<__nv_bfloat162*>(&ls);
        r0 += __bfloat162float(h2.x) + __bfloat162float(l2.x);
        r1 += __bfloat162float(h2.y) + __bfloat162float(l2.y);
    }
    if (s == 0 && tid < D2) {
        float run = 0.f;
#pragma unroll
        for (int c = 0; c < NCH; ++c) {
            int idx = (b * NCH + c) * D2 + tid;
            g_skP[idx] = run;
            run += g_sk[idx];
        }
    }
}

// ---------------------------------------------------------------------------
// Kernel C v4: chunk output (R14 version, passing)
// ---------------------------------------------------------------------------
#define ROW2 144
#define CW_QH  0
#define CW_QL  9216
#define CW_SH  18432
#define CW_SL  27648
#define CW_VH  36864
#define CW_VL  46080
#define CW_P0H 55296
#define CW_P0L 64512
#define CW_P1H 73728
#define CW_P1L 82944
#define CW_FLT 92160
#define SM_CO  (CW_FLT + 1792)

__global__ __launch_bounds__(256, 2) void chunk_out_hmma(const float* __restrict__ q,
                                                         const float* __restrict__ k,
                                                         const float* __restrict__ v) {
    extern __shared__ char smc[];
    const uint32_t sbase = smem_u32(smc);
    const int tid = threadIdx.x;
    const int wid = tid >> 5, lane = tid & 31;
    const int wm = wid & 3, wn = wid >> 2;
    const int b = blockIdx.x, c = blockIdx.y;

    float* sF = reinterpret_cast<float*>(smc + CW_FLT);
    if (tid < 64) {
        float ang = (float)(c * LCH + tid + 1) * ANG_K;
        sF[tid] = sinf(ang);
        sF[64 + tid] = cosf(ang);
    }
    if (tid < 128) sF[128 + tid] = g_skP[(b * NCH + c) * D2 + tid];

    const float4* qg = reinterpret_cast<const float4*>(q + ((size_t)b * TT + c * LCH) * HID);
    const float4* kg = reinterpret_cast<const float4*>(k + ((size_t)b * TT + c * LCH) * HID);
    for (int i = tid; i < 1024; i += 256) {
        int t = i >> 4, c4 = i & 15;
        float4 qv = qg[i];
        qv = make_float4(fmaxf(qv.x, 0.f), fmaxf(qv.y, 0.f), fmaxf(qv.z, 0.f), fmaxf(qv.w, 0.f));
        uint32_t h0, h1, l0, l1;
        split4(qv, h0, h1, l0, l1);
        *reinterpret_cast<uint2*>(smc + CW_QH + t * ROW2 + c4 * 8) = make_uint2(h0, h1);
        *reinterpret_cast<uint2*>(smc + CW_QL + t * ROW2 + c4 * 8) = make_uint2(l0, l1);
        float4 kv = kg[i];
        kv = make_float4(fmaxf(kv.x, 0.f), fmaxf(kv.y, 0.f), fmaxf(kv.z, 0.f), fmaxf(kv.w, 0.f));
        split4(kv, h0, h1, l0, l1);
        *reinterpret_cast<uint2*>(smc + CW_SH + t * ROW2 + c4 * 8) = make_uint2(h0, h1);
        *reinterpret_cast<uint2*>(smc + CW_SL + t * ROW2 + c4 * 8) = make_uint2(l0, l1);
    }
    {
        const float4* vg = reinterpret_cast<const float4*>(v);
        __nv_bfloat16* vh = reinterpret_cast<__nv_bfloat16*>(smc + CW_VH);
        __nv_bfloat16* vl = reinterpret_cast<__nv_bfloat16*>(smc + CW_VL);
        for (int i = tid; i < 1024; i += 256) {
            int tp = i >> 4, mq = i & 15;
            float4 x = vg[((size_t)(c * LCH + tp) * NHB + b) * 16 + mq];
            float xv[4] = {x.x, x.y, x.z, x.w};
#pragma unroll
            for (int e = 0; e < 4; ++e) {
                __nv_bfloat16 h, l;
                splitS(xv[e], h, l);
                vh[(4 * mq + e) * 72 + tp] = h;
                vl[(4 * mq + e) * 72 + tp] = l;
            }
        }
    }
    {
        const size_t basePT = ((size_t)((b * NCH + c) * 2)) * 4096;
        for (int i = tid; i < 1024; i += 256) {
            int half = i >> 9;
            int j = i & 511;
            int row = j >> 3, g = j & 7;
            size_t off = basePT + (size_t)half * 4096 + (size_t)row * 64 + g * 8;
            int dsth = half ? CW_P1H : CW_P0H;
            int dstl = half ? CW_P1L : CW_P0L;
            *reinterpret_cast<uint4*>(smc + dsth + row * ROW2 + g * 16) =
                *reinterpret_cast<const uint4*>(&g_PTH[off]);
            *reinterpret_cast<uint4*>(smc + dstl + row * ROW2 + g * 16) =
                *reinterpret_cast<const uint4*>(&g_PTL[off]);
        }
    }
    __syncthreads();

    const uint32_t aOffQ = (uint32_t)((wm * 16 + (lane & 15)) * ROW2 + ((lane >> 4) * 8) * 2);
    const uint32_t bOffB = (uint32_t)(((lane & 7) + ((lane >> 4) << 3)) * ROW2 +
                                      (((lane >> 3) & 1) * 8) * 2);

    float acc[4][4];
#pragma unroll
    for (int j = 0; j < 4; ++j)
#pragma unroll
        for (int e = 0; e < 4; ++e) acc[j][e] = 0.f;
    for (int ks = 0; ks < 4; ++ks) {
        const int ko = ks * 32;
        uint32_t ah[4], al[4];
        ldsm_x4(ah[0], ah[1], ah[2], ah[3], sbase + CW_QH + aOffQ + ko);
        ldsm_x4(al[0], al[1], al[2], al[3], sbase + CW_QL + aOffQ + ko);
#pragma unroll
        for (int pl = 0; pl < 2; ++pl) {
            const int p = wn * 2 + pl;
            if (p > wm) continue;
            uint32_t bh[4], bl[4];
            ldsm_x4(bh[0], bh[1], bh[2], bh[3], sbase + CW_SH + bOffB + p * 16 * ROW2 + ko);
            ldsm_x4(bl[0], bl[1], bl[2], bl[3], sbase + CW_SL + bOffB + p * 16 * ROW2 + ko);
            mma_bf16(acc[2*pl],   ah, bh);     mma_bf16(acc[2*pl],   ah, bl);
            mma_bf16(acc[2*pl],   al, bh);
            mma_bf16(acc[2*pl+1], ah, bh + 2); mma_bf16(acc[2*pl+1], ah, bl + 2);
            mma_bf16(acc[2*pl+1], al, bh + 2);
        }
    }

    const int gr = lane >> 2, gc = (lane & 3) * 2;
    const int r0 = wm * 16 + gr, r1 = r0 + 8;
    const float sr0 = sF[r0], cr0 = sF[64 + r0];
    const float sr1 = sF[r1], cr1 = sF[64 + r1];
    float rs0 = 0.f, rs1 = 0.f;
#pragma unroll
    for (int j = 0; j < 4; ++j) {
        int c0 = wn * 32 + j * 8 + gc, c1 = c0 + 1;
        float sc0 = sF[c0], cc0 = sF[64 + c0], sc1 = sF[c1], cc1 = sF[64 + c1];
        acc[j][0] = (c0 <= r0) ? acc[j][0] * (cr0 * cc0 + sr0 * sc0) : 0.f;
        acc[j][1] = (c1 <= r0) ? acc[j][1] * (cr0 * cc1 + sr0 * sc1) : 0.f;
        acc[j][2] = (c0 <= r1) ? acc[j][2] * (cr1 * cc0 + sr1 * sc0) : 0.f;
        acc[j][3] = (c1 <= r1) ? acc[j][3] * (cr1 * cc1 + sr1 * sc1) : 0.f;
        rs0 += acc[j][0] + acc[j][1];
        rs1 += acc[j][2] + acc[j][3];
    }
    rs0 += __shfl_xor_sync(0xFFFFFFFFu, rs0, 1); rs0 += __shfl_xor_sync(0xFFFFFFFFu, rs0, 2);
    rs1 += __shfl_xor_sync(0xFFFFFFFFu, rs1, 1); rs1 += __shfl_xor_sync(0xFFFFFFFFu, rs1, 2);
    if ((lane & 3) == 0) {
        sF[256 + wn * 64 + r0] = rs0;
        sF[256 + wn * 64 + r1] = rs1;
    }
    __syncthreads();

#pragma unroll
    for (int j = 0; j < 4; ++j) {
        int col = wn * 32 + j * 8 + gc;
        uint32_t hp, lp;
        split2(acc[j][0], acc[j][1], hp, lp);
        *reinterpret_cast<uint32_t*>(smc + CW_SH + r0 * ROW2 + col * 2) = hp;
        *reinterpret_cast<uint32_t*>(smc + CW_SL + r0 * ROW2 + col * 2) = lp;
        split2(acc[j][2], acc[j][3], hp, lp);
        *reinterpret_cast<uint32_t*>(smc + CW_SH + r1 * ROW2 + col * 2) = hp;
        *reinterpret_cast<uint32_t*>(smc + CW_SL + r1 * ROW2 + col * 2) = lp;
    }
    if (wn == 0) {
        float qd0 = 0.f, qd1 = 0.f;
        const __nv_bfloat16* qh = reinterpret_cast<const __nv_bfloat16*>(smc + CW_QH);
        const __nv_bfloat16* ql = reinterpret_cast<const __nv_bfloat16*>(smc + CW_QL);
        const int d0 = (lane & 3) * 16;
#pragma unroll
        for (int j = 0; j < 16; ++j) {
            int dl = d0 + j;
            float w0 = sr0 * sF[128 + dl] + cr0 * sF[192 + dl];
            float w1 = sr1 * sF[128 + dl] + cr1 * sF[192 + dl];
            float q0 = __bfloat162float(qh[r0 * 72 + dl]) + __bfloat162float(ql[r0 * 72 + dl]);
            float q1 = __bfloat162float(qh[r1 * 72 + dl]) + __bfloat162float(ql[r1 * 72 + dl]);
            qd0 += q0 * w0;
            qd1 += q1 * w1;
        }
        qd0 += __shfl_xor_sync(0xFFFFFFFFu, qd0, 1); qd0 += __shfl_xor_sync(0xFFFFFFFFu, qd0, 2);
        qd1 += __shfl_xor_sync(0xFFFFFFFFu, qd1, 1); qd1 += __shfl_xor_sync(0xFFFFFFFFu, qd1, 2);
        if ((lane & 3) == 0) {
            sF[384 + r0] = fmaxf(sF[256 + r0] + sF[320 + r0] + qd0, 1e-6f);
            sF[384 + r1] = fmaxf(sF[256 + r1] + sF[320 + r1] + qd1, 1e-6f);
        }
    }
    __syncthreads();

    float accO[4][4];
#pragma unroll
    for (int j = 0; j < 4; ++j)
#pragma unroll
        for (int e = 0; e < 4; ++e) accO[j][e] = 0.f;
    for (int ks = 0; ks < 4; ++ks) {
        const int ko = ks * 32;
        uint32_t ah[4], al[4];
        ldsm_x4(ah[0], ah[1], ah[2], ah[3], sbase + CW_SH + aOffQ + ko);
        ldsm_x4(al[0], al[1], al[2], al[3], sbase + CW_SL + aOffQ + ko);
#pragma unroll
        for (int pl = 0; pl < 2; ++pl) {
            const int p = wn * 2 + pl;
            uint32_t bh[4], bl[4];
            ldsm_x4(bh[0], bh[1], bh[2], bh[3], sbase + CW_VH + bOffB + p * 16 * ROW2 + ko);
            ldsm_x4(bl[0], bl[1], bl[2], bl[3], sbase + CW_VL + bOffB + p * 16 * ROW2 + ko);
            mma_bf16(accO[2*pl],   ah, bh);     mma_bf16(accO[2*pl],   ah, bl);
            mma_bf16(accO[2*pl],   al, bh);
            mma_bf16(accO[2*pl+1], ah, bh + 2); mma_bf16(accO[2*pl+1], ah, bl + 2);
            mma_bf16(accO[2*pl+1], al, bh + 2);
        }
    }
#pragma unroll
    for (int half = 0; half < 2; ++half) {
        const int ph = half ? CW_P1H : CW_P0H;
        const int plo = half ? CW_P1L : CW_P0L;
        float accT[4][4];
#pragma unroll
        for (int j = 0; j < 4; ++j)
#pragma unroll
            for (int e = 0; e < 4; ++e) accT[j][e] = 0.f;
        for (int ks = 0; ks < 4; ++ks) {
            const int ko = ks * 32;
            uint32_t ah[4], al[4];
            ldsm_x4(ah[0], ah[1], ah[2], ah[3], sbase + CW_QH + aOffQ + ko);
            ldsm_x4(al[0], al[1], al[2], al[3], sbase + CW_QL + aOffQ + ko);
#pragma unroll
            for (int pl = 0; pl < 2; ++pl) {
                const int p = wn * 2 + pl;
                uint32_t bh[4], bl[4];
                ldsm_x4(bh[0], bh[1], bh[2], bh[3], sbase + ph  + bOffB + p * 16 * ROW2 + ko);
                ldsm_x4(bl[0], bl[1], bl[2], bl[3], sbase + plo + bOffB + p * 16 * ROW2 + ko);
                mma_bf16(accT[2*pl],   ah, bh);     mma_bf16(accT[2*pl],   ah, bl);
                mma_bf16(accT[2*pl],   al, bh);
                mma_bf16(accT[2*pl+1], ah, bh + 2); mma_bf16(accT[2*pl+1], ah, bl + 2);
                mma_bf16(accT[2*pl+1], al, bh + 2);
            }
        }
        const float w0 = half ? cr0 : sr0;
        const float w1 = half ? cr1 : sr1;
#pragma unroll
        for (int j = 0; j < 4; ++j) {
            accO[j][0] += w0 * accT[j][0];
            accO[j][1] += w0 * accT[j][1];
            accO[j][2] += w1 * accT[j][2];
            accO[j][3] += w1 * accT[j][3];
        }
    }

    const float inv0 = 1.0f / sF[384 + r0], inv1 = 1.0f / sF[384 + r1];
    const int n = b >> 3, hh = b & 7;
    const size_t base0 = ((size_t)(c * LCH + r0) * NB + n) * EMB + hh * HID;
    const size_t base1 = ((size_t)(c * LCH + r1) * NB + n) * EMB + hh * HID;
#pragma unroll
    for (int j = 0; j < 4; ++j) {
        int col = wn * 32 + j * 8 + gc;
        uint32_t hp, lp;
        split2(accO[j][0] * inv0, accO[j][1] * inv0, hp, lp);
        *reinterpret_cast<uint32_t*>(&g_attnH[base0 + col]) = hp;
        *reinterpret_cast<uint32_t*>(&g_attnL[base0 + col]) = lp;
        split2(accO[j][2] * inv1, accO[j][3] * inv1, hp, lp);
        *reinterpret_cast<uint32_t*>(&g_attnH[base1 + col]) = hp;
        *reinterpret_cast<uint32_t*>(&g_attnL[base1 + col]) = lp;
    }
}

// ---------------------------------------------------------------------------
// Kernel D v7b: outproj cp.async pipeline, now 3 CTAs/SM
// ---------------------------------------------------------------------------
#define ROWB2 144
#define BUF_BYTES (4 * 64 * ROWB2)
#define OAH2 0
#define OAL2 (64 * ROWB2)
#define OBH2 (2 * 64 * ROWB2)
#define OBL2 (3 * 64 * ROWB2)
#define SM_HMMA (2 * BUF_BYTES)

__global__ __launch_bounds__(256, 3) void outproj_hmma_kernel(const float* __restrict__ bias,
                                                              float* __restrict__ out) {
    extern __shared__ char smc[];
    const uint32_t sbase = smem_u32(smc);
    const int tid = threadIdx.x;
    const int wid = tid >> 5, lane = tid & 31;
    const int wm = wid & 3, wn = wid >> 2;
    const int rb = blockIdx.x * 64;
    const int nb = blockIdx.y * 64;

    float acc[4][4];
#pragma unroll
    for (int nt = 0; nt < 4; ++nt)
#pragma unroll
        for (int e = 0; e < 4; ++e) acc[nt][e] = 0.f;

    auto stage = [&](int kc, int bufIdx) {
        const uint32_t bufs = sbase + bufIdx * BUF_BYTES;
        const size_t kbase = (size_t)kc * 64;
#pragma unroll
        for (int j = 0; j < 8; ++j) {
            int i = tid + j * 256;
            int arr = i >> 9;
            int jj = i & 511;
            int row = jj >> 3, g = jj & 7;
            const __nv_bfloat16* srcp;
            uint32_t dst;
            if (arr == 0) {
                srcp = &g_attnH[(size_t)(rb + row) * EMB + kbase + g * 8];
                dst = bufs + OAH2 + row * ROWB2 + g * 16;
            } else if (arr == 1) {
                srcp = &g_attnL[(size_t)(rb + row) * EMB + kbase + g * 8];
                dst = bufs + OAL2 + row * ROWB2 + g * 16;
            } else if (arr == 2) {
                srcp = &g_WH[(size_t)(nb + row) * EMB + kbase + g * 8];
                dst = bufs + OBH2 + row * ROWB2 + g * 16;
            } else {
                srcp = &g_WL[(size_t)(nb + row) * EMB + kbase + g * 8];
                dst = bufs + OBL2 + row * ROWB2 + g * 16;
            }
            cp16(dst, srcp);
        }
        CP_COMMIT();
    };

    const uint32_t aOff = (uint32_t)((wm * 16 + (lane & 15)) * ROWB2 + ((lane >> 4) * 8) * 2);
    const uint32_t bOff = (uint32_t)((wn * 32 + (lane & 7) + ((lane >> 4) << 3)) * ROWB2 +
                                     (((lane >> 3) & 1) * 8) * 2);

    stage(0, 0);
    for (int kc = 0; kc < 8; ++kc) {
        if (kc < 7) stage(kc + 1, (kc + 1) & 1);
        if (kc < 7) { CP_WAIT(1); } else { CP_WAIT(0); }
        __syncthreads();

        const uint32_t bufs = sbase + (kc & 1) * BUF_BYTES;
#pragma unroll
        for (int ks = 0; ks < 4; ++ks) {
            const int ko = ks * 32;
            uint32_t ah[4], al[4];
            ldsm_x4(ah[0], ah[1], ah[2], ah[3], bufs + OAH2 + aOff + ko);
            ldsm_x4(al[0], al[1], al[2], al[3], bufs + OAL2 + aOff + ko);
            uint32_t bh[4][2], bl[4][2];
#pragma unroll
            for (int p = 0; p < 2; ++p) {
                ldsm_x4(bh[2*p][0], bh[2*p][1], bh[2*p+1][0], bh[2*p+1][1],
                        bufs + OBH2 + bOff + p * 16 * ROWB2 + ko);
                ldsm_x4(bl[2*p][0], bl[2*p][1], bl[2*p+1][0], bl[2*p+1][1],
                        bufs + OBL2 + bOff + p * 16 * ROWB2 + ko);
            }
#pragma unroll
            for (int nt = 0; nt < 4; ++nt) {
                mma_bf16(acc[nt], ah, bh[nt]);
                mma_bf16(acc[nt], ah, bl[nt]);
                mma_bf16(acc[nt], al, bh[nt]);
            }
        }
        __syncthreads();
    }

    const int gr = lane >> 2, gc = (lane & 3) * 2;
    const int h = blockIdx.y;
#pragma unroll
    for (int nt = 0; nt < 4; ++nt) {
        int d = wn * 32 + nt * 8 + gc;
        float b0 = bias[nb + d], b1 = bias[nb + d + 1];
#pragma unroll
        for (int half = 0; half < 2; ++half) {
            int r = rb + wm * 16 + gr + half * 8;
            int t = r >> 1, n = r & 1;
            size_t oidx = (((size_t)(n * HH + h) * TT) + t) * HID + d;
            *reinterpret_cast<float2*>(out + oidx) =
                make_float2(acc[nt][half * 2 + 0] + b0,
                            acc[nt][half * 2 + 1] + b1);
        }
    }
}

// ---------------------------------------------------------------------------
// Launch
// ---------------------------------------------------------------------------
extern "C" void kernel_launch(void* const* d_in, const int* in_sizes, int n_in,
                              void* d_out, int out_size) {
    const float* q    = (const float*)d_in[0];
    const float* k    = (const float*)d_in[1];
    const float* v    = (const float*)d_in[2];
    const float* W    = (const float*)d_in[3];
    const float* bias = (const float*)d_in[4];
    float* out = (float*)d_out;

    static cudaStream_t s_side = nullptr;
    static cudaEvent_t evF = nullptr, evJ = nullptr;
    if (!s_side) {
        cudaStreamCreateWithFlags(&s_side, cudaStreamNonBlocking);
        cudaEventCreateWithFlags(&evF, cudaEventDisableTiming);
        cudaEventCreateWithFlags(&evJ, cudaEventDisableTiming);
    }

    cudaFuncSetAttribute(chunk_out_hmma,
                         cudaFuncAttributeMaxDynamicSharedMemorySize, SM_CO);
    cudaFuncSetAttribute(outproj_hmma_kernel,
                         cudaFuncAttributeMaxDynamicSharedMemorySize, SM_HMMA);

    const bool has_probs = (out_size > CTX_ELEMS);
    if (has_probs) {
        cudaEventRecord(evF, 0);
        cudaStreamWaitEvent(s_side, evF, 0);
        cudaMemsetAsync(out + CTX_ELEMS, 0,
                        (size_t)(out_size - CTX_ELEMS) * sizeof(float), s_side);
        cudaEventRecord(evJ, s_side);
    }

    chunk_sums_kernel<<<dim3(NHB, NCH + 4), 256, 33280>>>(k, v, W);
    prefix_kernel<<<dim3(NHB, NCH), 256>>>();
    chunk_out_hmma<<<dim3(NHB, NCH), 256, SM_CO>>>(q, k, v);
    outproj_hmma_kernel<<<dim3(32, 8), 256, SM_HMMA>>>(bias, out);

    if (has_probs) cudaStreamWaitEvent(0, evJ, 0);
}

// round 17
// speedup vs baseline: 3.7318x; 1.0322x over previous
#include <cuda_runtime.h>
#include <cuda_bf16.h>
#include <stdint.h>
#include <math.h>

// Problem constants
#define NB   2
#define HH   8
#define TT   1024
#define HID  64
#define NHB  (NB*HH)
#define D2   (2*HID)
#define EMB  (HH*HID)          // 512
#define LCH  64
#define NCH  (TT/LCH)          // 16
#define CTX_ELEMS (NB*HH*TT*HID)
#define ANG_K 0.0015339807878856412f

typedef unsigned long long u64t;

__device__ __forceinline__ u64t pack2(float lo, float hi) {
    u64t r; asm("mov.b64 %0, {%1, %2};" : "=l"(r) : "f"(lo), "f"(hi)); return r;
}
__device__ __forceinline__ float2 unpack2(u64t p) {
    float2 r; asm("mov.b64 {%0, %1}, %2;" : "=f"(r.x), "=f"(r.y) : "l"(p)); return r;
}
__device__ __forceinline__ void fma2(u64t& d, u64t a, u64t b) {
    asm("fma.rn.f32x2 %0, %1, %2, %0;" : "+l"(d) : "l"(a), "l"(b));
}
__device__ __forceinline__ void mul2(u64t& d, u64t a, u64t b) {
    asm("mul.rn.f32x2 %0, %1, %2;" : "=l"(d) : "l"(a), "l"(b));
}
__device__ __forceinline__ uint32_t smem_u32(const void* p) {
    uint32_t a;
    asm("{ .reg .u64 t; cvta.to.shared.u64 t, %1; cvt.u32.u64 %0, t; }" : "=r"(a) : "l"(p));
    return a;
}
#define PDL_WAIT() asm volatile("griddepcontrol.wait;" ::: "memory")

// ---- warp MMA + cp.async helpers (verified R8-R16) ----
__device__ __forceinline__ void ldsm_x4(uint32_t& r0, uint32_t& r1, uint32_t& r2, uint32_t& r3,
                                        uint32_t addr) {
    asm volatile("ldmatrix.sync.aligned.m8n8.x4.shared.b16 {%0,%1,%2,%3}, [%4];"
                 : "=r"(r0), "=r"(r1), "=r"(r2), "=r"(r3) : "r"(addr));
}
__device__ __forceinline__ void mma_bf16(float* c, const uint32_t* a, const uint32_t* b) {
    asm volatile("mma.sync.aligned.m16n8k16.row.col.f32.bf16.bf16.f32 "
                 "{%0,%1,%2,%3}, {%4,%5,%6,%7}, {%8,%9}, {%0,%1,%2,%3};"
                 : "+f"(c[0]), "+f"(c[1]), "+f"(c[2]), "+f"(c[3])
                 : "r"(a[0]), "r"(a[1]), "r"(a[2]), "r"(a[3]), "r"(b[0]), "r"(b[1]));
}
__device__ __forceinline__ void cp16(uint32_t dst, const void* src) {
    asm volatile("cp.async.ca.shared.global [%0], [%1], 16;" :: "r"(dst), "l"(src));
}
#define CP_COMMIT()  asm volatile("cp.async.commit_group;" ::: "memory")
#define CP_WAIT(n)   asm volatile("cp.async.wait_group %0;" :: "n"(n) : "memory")

__device__ __forceinline__ void split4(float4 x, uint32_t& h0, uint32_t& h1,
                                       uint32_t& l0, uint32_t& l1) {
    __nv_bfloat16 a = __float2bfloat16(x.x), b = __float2bfloat16(x.y),
                  c = __float2bfloat16(x.z), d = __float2bfloat16(x.w);
    __nv_bfloat162 hA(a, b), hB(c, d);
    h0 = *reinterpret_cast<uint32_t*>(&hA);
    h1 = *reinterpret_cast<uint32_t*>(&hB);
    __nv_bfloat162 lA(__float2bfloat16(x.x - __bfloat162float(a)),
                      __float2bfloat16(x.y - __bfloat162float(b)));
    __nv_bfloat162 lB(__float2bfloat16(x.z - __bfloat162float(c)),
                      __float2bfloat16(x.w - __bfloat162float(d)));
    l0 = *reinterpret_cast<uint32_t*>(&lA);
    l1 = *reinterpret_cast<uint32_t*>(&lB);
}
__device__ __forceinline__ void split2(float v0, float v1, uint32_t& hp, uint32_t& lp) {
    __nv_bfloat16 h0 = __float2bfloat16(v0), h1 = __float2bfloat16(v1);
    __nv_bfloat162 hv(h0, h1);
    hp = *reinterpret_cast<uint32_t*>(&hv);
    __nv_bfloat162 lv(__float2bfloat16(v0 - __bfloat162float(h0)),
                      __float2bfloat16(v1 - __bfloat162float(h1)));
    lp = *reinterpret_cast<uint32_t*>(&lv);
}
__device__ __forceinline__ void splitS(float v, __nv_bfloat16& h, __nv_bfloat16& l) {
    h = __float2bfloat16(v);
    l = __float2bfloat16(v - __bfloat162float(h));
}

// Scratch (device globals)
__device__ __align__(16) __nv_bfloat16 g_STH[NHB*NCH*2*64*64];
__device__ __align__(16) __nv_bfloat16 g_STL[NHB*NCH*2*64*64];
__device__ __align__(16) __nv_bfloat16 g_PTH[NHB*NCH*2*64*64];
__device__ __align__(16) __nv_bfloat16 g_PTL[NHB*NCH*2*64*64];
__device__ float g_sk  [NHB*NCH*D2];
__device__ float g_skP [NHB*NCH*D2];
__device__ __align__(16) __nv_bfloat16 g_attnH[TT*NB*EMB];
__device__ __align__(16) __nv_bfloat16 g_attnL[TT*NB*EMB];
__device__ __align__(16) __nv_bfloat16 g_WH[EMB*EMB];
__device__ __align__(16) __nv_bfloat16 g_WL[EMB*EMB];

// ---------------------------------------------------------------------------
// Kernel A+W fused (unchanged, passing)
// ---------------------------------------------------------------------------
__global__ __launch_bounds__(256) void chunk_sums_kernel(const float* __restrict__ k,
                                                         const float* __restrict__ v,
                                                         const float* __restrict__ W) {
    extern __shared__ float sm[];
    const int tid = threadIdx.x;

    if (blockIdx.y >= NCH) {
        const int blk = blockIdx.x + (blockIdx.y - NCH) * 16;
        const int gt = blk * 256 + tid;
        const float4* W4 = reinterpret_cast<const float4*>(W);
#pragma unroll
        for (int j = 0; j < 4; ++j) {
            int idx = j * 16384 + gt;
            float4 x = W4[idx];
            uint32_t h0, h1, l0, l1;
            split4(x, h0, h1, l0, l1);
            *reinterpret_cast<uint2*>(&g_WH[idx * 4]) = make_uint2(h0, h1);
            *reinterpret_cast<uint2*>(&g_WL[idx * 4]) = make_uint2(l0, l1);
        }
        return;
    }

    float* sK   = sm;
    float* sV   = sm + 4096;
    float* sSin = sm + 8192;
    float* sCos = sm + 8256;
    const int b = blockIdx.x, c = blockIdx.y;

    if (tid < LCH) {
        float ang = (float)(c * LCH + tid + 1) * ANG_K;
        sSin[tid] = sinf(ang);
        sCos[tid] = cosf(ang);
    }
    const float4* kg = reinterpret_cast<const float4*>(k + ((size_t)b * TT + c * LCH) * HID);
    float4* sK4w = reinterpret_cast<float4*>(sK);
    for (int i = tid; i < LCH * 16; i += 256) {
        float4 kv = kg[i];
        sK4w[i] = make_float4(fmaxf(kv.x, 0.f), fmaxf(kv.y, 0.f),
                              fmaxf(kv.z, 0.f), fmaxf(kv.w, 0.f));
    }
    const float4* vg = reinterpret_cast<const float4*>(v);
    float4* sV4w = reinterpret_cast<float4*>(sV);
    for (int i = tid; i < LCH * 16; i += 256) {
        int t = i >> 4, c4 = i & 15;
        sV4w[t * 16 + c4] = vg[((size_t)(c * LCH + t) * NHB + b) * 16 + c4];
    }
    __syncthreads();

    const int tx = tid & 15, ty = tid >> 4;
    const int m0 = tx * 4;
    const float* wT = (ty < 8) ? sSin : sCos;
    u64t acc[8][2];
#pragma unroll
    for (int i = 0; i < 8; ++i) { acc[i][0] = pack2(0.f, 0.f); acc[i][1] = pack2(0.f, 0.f); }

    const float4* sK4 = reinterpret_cast<const float4*>(sK);
    const float4* sV4 = reinterpret_cast<const float4*>(sV);
    for (int t = 0; t < LCH; ++t) {
        float4 a0 = sK4[t * 16 + (ty & 7) * 2];
        float4 a1 = sK4[t * 16 + (ty & 7) * 2 + 1];
        float4 bv = sV4[t * 16 + tx];
        float w = wT[t];
        u64t wp = pack2(w, w);
        u64t b01 = pack2(bv.x, bv.y), b23 = pack2(bv.z, bv.w);
        mul2(b01, b01, wp);
        mul2(b23, b23, wp);
        float av[8] = {a0.x, a0.y, a0.z, a0.w, a1.x, a1.y, a1.z, a1.w};
#pragma unroll
        for (int i = 0; i < 8; ++i) {
            u64t ad = pack2(av[i], av[i]);
            fma2(acc[i][0], ad, b01);
            fma2(acc[i][1], ad, b23);
        }
    }

    const int half = ty >> 3;
    const int draw = (ty & 7) * 8;
    const size_t base = ((size_t)((b * NCH + c) * 2 + half)) * 4096;
#pragma unroll
    for (int j = 0; j < 4; ++j) {
        float vals[8];
#pragma unroll
        for (int i = 0; i < 8; ++i) {
            float2 pp = unpack2(acc[i][j >> 1]);
            vals[i] = (j & 1) ? pp.y : pp.x;
        }
        uint32_t hw[4], lw[4];
#pragma unroll
        for (int g = 0; g < 4; ++g) {
            uint32_t hp, lp;
            split2(vals[2 * g], vals[2 * g + 1], hp, lp);
            hw[g] = hp; lw[g] = lp;
        }
        size_t off = base + (size_t)(m0 + j) * 64 + draw;
        *reinterpret_cast<uint4*>(&g_STH[off]) = make_uint4(hw[0], hw[1], hw[2], hw[3]);
        *reinterpret_cast<uint4*>(&g_STL[off]) = make_uint4(lw[0], lw[1], lw[2], lw[3]);
    }

    if (tid < D2) {
        int dl = tid & 63;
        const float* wv = (tid < 64) ? sSin : sCos;
        float s = 0.f;
        for (int t = 0; t < LCH; ++t) s += wv[t] * sK[t * HID + dl];
        g_sk[(b * NCH + c) * D2 + tid] = s;
    }
}

// ---------------------------------------------------------------------------
// Kernel B: exclusive prefix (PDL wait at top)
// ---------------------------------------------------------------------------
__global__ __launch_bounds__(256) void prefix_kernel() {
    PDL_WAIT();
    const int b = blockIdx.x, s = blockIdx.y, tid = threadIdx.x;
    const int e = s * 256 + tid;
    float r0 = 0.f, r1 = 0.f;
#pragma unroll
    for (int c = 0; c < NCH; ++c) {
        size_t idx = ((size_t)(b * NCH + c)) * 8192 + (size_t)e * 2;
        uint32_t hp, lp;
        split2(r0, r1, hp, lp);
        *reinterpret_cast<uint32_t*>(&g_PTH[idx]) = hp;
        *reinterpret_cast<uint32_t*>(&g_PTL[idx]) = lp;
        uint32_t hs = *reinterpret_cast<const uint32_t*>(&g_STH[idx]);
        uint32_t ls = *reinterpret_cast<const uint32_t*>(&g_STL[idx]);
        __nv_bfloat162 h2 = *reinterpret_cast<__nv_bfloat162*>(&hs);
        __nv_bfloat162 l2 = *reinterpret_cast<__nv_bfloat162*>(&ls);
        r0 += __bfloat162float(h2.x) + __bfloat162float(l2.x);
        r1 += __bfloat162float(h2.y) + __bfloat162float(l2.y);
    }
    if (s == 0 && tid < D2) {
        float run = 0.f;
#pragma unroll
        for (int c = 0; c < NCH; ++c) {
            int idx = (b * NCH + c) * D2 + tid;
            g_skP[idx] = run;
            run += g_sk[idx];
        }
    }
}

// ---------------------------------------------------------------------------
// Kernel C v5: chunk output; independent staging BEFORE the PDL wait
// ---------------------------------------------------------------------------
#define ROW2 144
#define CW_QH  0
#define CW_QL  9216
#define CW_SH  18432
#define CW_SL  27648
#define CW_VH  36864
#define CW_VL  46080
#define CW_P0H 55296
#define CW_P0L 64512
#define CW_P1H 73728
#define CW_P1L 82944
#define CW_FLT 92160
#define SM_CO  (CW_FLT + 1792)

__global__ __launch_bounds__(256, 2) void chunk_out_hmma(const float* __restrict__ q,
                                                         const float* __restrict__ k,
                                                         const float* __restrict__ v) {
    extern __shared__ char smc[];
    const uint32_t sbase = smem_u32(smc);
    const int tid = threadIdx.x;
    const int wid = tid >> 5, lane = tid & 31;
    const int wm = wid & 3, wn = wid >> 2;
    const int b = blockIdx.x, c = blockIdx.y;

    float* sF = reinterpret_cast<float*>(smc + CW_FLT);
    if (tid < 64) {
        float ang = (float)(c * LCH + tid + 1) * ANG_K;
        sF[tid] = sinf(ang);
        sF[64 + tid] = cosf(ang);
    }

    // ---- independent staging (overlaps prefix via PDL early launch) ----
    const float4* qg = reinterpret_cast<const float4*>(q + ((size_t)b * TT + c * LCH) * HID);
    const float4* kg = reinterpret_cast<const float4*>(k + ((size_t)b * TT + c * LCH) * HID);
    for (int i = tid; i < 1024; i += 256) {
        int t = i >> 4, c4 = i & 15;
        float4 qv = qg[i];
        qv = make_float4(fmaxf(qv.x, 0.f), fmaxf(qv.y, 0.f), fmaxf(qv.z, 0.f), fmaxf(qv.w, 0.f));
        uint32_t h0, h1, l0, l1;
        split4(qv, h0, h1, l0, l1);
        *reinterpret_cast<uint2*>(smc + CW_QH + t * ROW2 + c4 * 8) = make_uint2(h0, h1);
        *reinterpret_cast<uint2*>(smc + CW_QL + t * ROW2 + c4 * 8) = make_uint2(l0, l1);
        float4 kv = kg[i];
        kv = make_float4(fmaxf(kv.x, 0.f), fmaxf(kv.y, 0.f), fmaxf(kv.z, 0.f), fmaxf(kv.w, 0.f));
        split4(kv, h0, h1, l0, l1);
        *reinterpret_cast<uint2*>(smc + CW_SH + t * ROW2 + c4 * 8) = make_uint2(h0, h1);
        *reinterpret_cast<uint2*>(smc + CW_SL + t * ROW2 + c4 * 8) = make_uint2(l0, l1);
    }
    {
        const float4* vg = reinterpret_cast<const float4*>(v);
        __nv_bfloat16* vh = reinterpret_cast<__nv_bfloat16*>(smc + CW_VH);
        __nv_bfloat16* vl = reinterpret_cast<__nv_bfloat16*>(smc + CW_VL);
        for (int i = tid; i < 1024; i += 256) {
            int tp = i >> 4, mq = i & 15;
            float4 x = vg[((size_t)(c * LCH + tp) * NHB + b) * 16 + mq];
            float xv[4] = {x.x, x.y, x.z, x.w};
#pragma unroll
            for (int e = 0; e < 4; ++e) {
                __nv_bfloat16 h, l;
                splitS(xv[e], h, l);
                vh[(4 * mq + e) * 72 + tp] = h;
                vl[(4 * mq + e) * 72 + tp] = l;
            }
        }
    }

    // ---- dependent staging: wait for prefix, then skP + P halves ----
    PDL_WAIT();
    if (tid < 128) sF[128 + tid] = g_skP[(b * NCH + c) * D2 + tid];
    {
        const size_t basePT = ((size_t)((b * NCH + c) * 2)) * 4096;
        for (int i = tid; i < 1024; i += 256) {
            int half = i >> 9;
            int j = i & 511;
            int row = j >> 3, g = j & 7;
            size_t off = basePT + (size_t)half * 4096 + (size_t)row * 64 + g * 8;
            int dsth = half ? CW_P1H : CW_P0H;
            int dstl = half ? CW_P1L : CW_P0L;
            *reinterpret_cast<uint4*>(smc + dsth + row * ROW2 + g * 16) =
                *reinterpret_cast<const uint4*>(&g_PTH[off]);
            *reinterpret_cast<uint4*>(smc + dstl + row * ROW2 + g * 16) =
                *reinterpret_cast<const uint4*>(&g_PTL[off]);
        }
    }
    __syncthreads();

    const uint32_t aOffQ = (uint32_t)((wm * 16 + (lane & 15)) * ROW2 + ((lane >> 4) * 8) * 2);
    const uint32_t bOffB = (uint32_t)(((lane & 7) + ((lane >> 4) << 3)) * ROW2 +
                                      (((lane >> 3) & 1) * 8) * 2);

    float acc[4][4];
#pragma unroll
    for (int j = 0; j < 4; ++j)
#pragma unroll
        for (int e = 0; e < 4; ++e) acc[j][e] = 0.f;
    for (int ks = 0; ks < 4; ++ks) {
        const int ko = ks * 32;
        uint32_t ah[4], al[4];
        ldsm_x4(ah[0], ah[1], ah[2], ah[3], sbase + CW_QH + aOffQ + ko);
        ldsm_x4(al[0], al[1], al[2], al[3], sbase + CW_QL + aOffQ + ko);
#pragma unroll
        for (int pl = 0; pl < 2; ++pl) {
            const int p = wn * 2 + pl;
            if (p > wm) continue;
            uint32_t bh[4], bl[4];
            ldsm_x4(bh[0], bh[1], bh[2], bh[3], sbase + CW_SH + bOffB + p * 16 * ROW2 + ko);
            ldsm_x4(bl[0], bl[1], bl[2], bl[3], sbase + CW_SL + bOffB + p * 16 * ROW2 + ko);
            mma_bf16(acc[2*pl],   ah, bh);     mma_bf16(acc[2*pl],   ah, bl);
            mma_bf16(acc[2*pl],   al, bh);
            mma_bf16(acc[2*pl+1], ah, bh + 2); mma_bf16(acc[2*pl+1], ah, bl + 2);
            mma_bf16(acc[2*pl+1], al, bh + 2);
        }
    }

    const int gr = lane >> 2, gc = (lane & 3) * 2;
    const int r0 = wm * 16 + gr, r1 = r0 + 8;
    const float sr0 = sF[r0], cr0 = sF[64 + r0];
    const float sr1 = sF[r1], cr1 = sF[64 + r1];
    float rs0 = 0.f, rs1 = 0.f;
#pragma unroll
    for (int j = 0; j < 4; ++j) {
        int c0 = wn * 32 + j * 8 + gc, c1 = c0 + 1;
        float sc0 = sF[c0], cc0 = sF[64 + c0], sc1 = sF[c1], cc1 = sF[64 + c1];
        acc[j][0] = (c0 <= r0) ? acc[j][0] * (cr0 * cc0 + sr0 * sc0) : 0.f;
        acc[j][1] = (c1 <= r0) ? acc[j][1] * (cr0 * cc1 + sr0 * sc1) : 0.f;
        acc[j][2] = (c0 <= r1) ? acc[j][2] * (cr1 * cc0 + sr1 * sc0) : 0.f;
        acc[j][3] = (c1 <= r1) ? acc[j][3] * (cr1 * cc1 + sr1 * sc1) : 0.f;
        rs0 += acc[j][0] + acc[j][1];
        rs1 += acc[j][2] + acc[j][3];
    }
    rs0 += __shfl_xor_sync(0xFFFFFFFFu, rs0, 1); rs0 += __shfl_xor_sync(0xFFFFFFFFu, rs0, 2);
    rs1 += __shfl_xor_sync(0xFFFFFFFFu, rs1, 1); rs1 += __shfl_xor_sync(0xFFFFFFFFu, rs1, 2);
    if ((lane & 3) == 0) {
        sF[256 + wn * 64 + r0] = rs0;
        sF[256 + wn * 64 + r1] = rs1;
    }
    __syncthreads();

#pragma unroll
    for (int j = 0; j < 4; ++j) {
        int col = wn * 32 + j * 8 + gc;
        uint32_t hp, lp;
        split2(acc[j][0], acc[j][1], hp, lp);
        *reinterpret_cast<uint32_t*>(smc + CW_SH + r0 * ROW2 + col * 2) = hp;
        *reinterpret_cast<uint32_t*>(smc + CW_SL + r0 * ROW2 + col * 2) = lp;
        split2(acc[j][2], acc[j][3], hp, lp);
        *reinterpret_cast<uint32_t*>(smc + CW_SH + r1 * ROW2 + col * 2) = hp;
        *reinterpret_cast<uint32_t*>(smc + CW_SL + r1 * ROW2 + col * 2) = lp;
    }
    if (wn == 0) {
        float qd0 = 0.f, qd1 = 0.f;
        const __nv_bfloat16* qh = reinterpret_cast<const __nv_bfloat16*>(smc + CW_QH);
        const __nv_bfloat16* ql = reinterpret_cast<const __nv_bfloat16*>(smc + CW_QL);
        const int d0 = (lane & 3) * 16;
#pragma unroll
        for (int j = 0; j < 16; ++j) {
            int dl = d0 + j;
            float w0 = sr0 * sF[128 + dl] + cr0 * sF[192 + dl];
            float w1 = sr1 * sF[128 + dl] + cr1 * sF[192 + dl];
            float q0 = __bfloat162float(qh[r0 * 72 + dl]) + __bfloat162float(ql[r0 * 72 + dl]);
            float q1 = __bfloat162float(qh[r1 * 72 + dl]) + __bfloat162float(ql[r1 * 72 + dl]);
            qd0 += q0 * w0;
            qd1 += q1 * w1;
        }
        qd0 += __shfl_xor_sync(0xFFFFFFFFu, qd0, 1); qd0 += __shfl_xor_sync(0xFFFFFFFFu, qd0, 2);
        qd1 += __shfl_xor_sync(0xFFFFFFFFu, qd1, 1); qd1 += __shfl_xor_sync(0xFFFFFFFFu, qd1, 2);
        if ((lane & 3) == 0) {
            sF[384 + r0] = fmaxf(sF[256 + r0] + sF[320 + r0] + qd0, 1e-6f);
            sF[384 + r1] = fmaxf(sF[256 + r1] + sF[320 + r1] + qd1, 1e-6f);
        }
    }
    __syncthreads();

    float accO[4][4];
#pragma unroll
    for (int j = 0; j < 4; ++j)
#pragma unroll
        for (int e = 0; e < 4; ++e) accO[j][e] = 0.f;
    for (int ks = 0; ks < 4; ++ks) {
        const int ko = ks * 32;
        uint32_t ah[4], al[4];
        ldsm_x4(ah[0], ah[1], ah[2], ah[3], sbase + CW_SH + aOffQ + ko);
        ldsm_x4(al[0], al[1], al[2], al[3], sbase + CW_SL + aOffQ + ko);
#pragma unroll
        for (int pl = 0; pl < 2; ++pl) {
            const int p = wn * 2 + pl;
            uint32_t bh[4], bl[4];
            ldsm_x4(bh[0], bh[1], bh[2], bh[3], sbase + CW_VH + bOffB + p * 16 * ROW2 + ko);
            ldsm_x4(bl[0], bl[1], bl[2], bl[3], sbase + CW_VL + bOffB + p * 16 * ROW2 + ko);
            mma_bf16(accO[2*pl],   ah, bh);     mma_bf16(accO[2*pl],   ah, bl);
            mma_bf16(accO[2*pl],   al, bh);
            mma_bf16(accO[2*pl+1], ah, bh + 2); mma_bf16(accO[2*pl+1], ah, bl + 2);
            mma_bf16(accO[2*pl+1], al, bh + 2);
        }
    }
#pragma unroll
    for (int half = 0; half < 2; ++half) {
        const int ph = half ? CW_P1H : CW_P0H;
        const int plo = half ? CW_P1L : CW_P0L;
        float accT[4][4];
#pragma unroll
        for (int j = 0; j < 4; ++j)
#pragma unroll
            for (int e = 0; e < 4; ++e) accT[j][e] = 0.f;
        for (int ks = 0; ks < 4; ++ks) {
            const int ko = ks * 32;
            uint32_t ah[4], al[4];
            ldsm_x4(ah[0], ah[1], ah[2], ah[3], sbase + CW_QH + aOffQ + ko);
            ldsm_x4(al[0], al[1], al[2], al[3], sbase + CW_QL + aOffQ + ko);
#pragma unroll
            for (int pl = 0; pl < 2; ++pl) {
                const int p = wn * 2 + pl;
                uint32_t bh[4], bl[4];
                ldsm_x4(bh[0], bh[1], bh[2], bh[3], sbase + ph  + bOffB + p * 16 * ROW2 + ko);
                ldsm_x4(bl[0], bl[1], bl[2], bl[3], sbase + plo + bOffB + p * 16 * ROW2 + ko);
                mma_bf16(accT[2*pl],   ah, bh);     mma_bf16(accT[2*pl],   ah, bl);
                mma_bf16(accT[2*pl],   al, bh);
                mma_bf16(accT[2*pl+1], ah, bh + 2); mma_bf16(accT[2*pl+1], ah, bl + 2);
                mma_bf16(accT[2*pl+1], al, bh + 2);
            }
        }
        const float w0 = half ? cr0 : sr0;
        const float w1 = half ? cr1 : sr1;
#pragma unroll
        for (int j = 0; j < 4; ++j) {
            accO[j][0] += w0 * accT[j][0];
            accO[j][1] += w0 * accT[j][1];
            accO[j][2] += w1 * accT[j][2];
            accO[j][3] += w1 * accT[j][3];
        }
    }

    const float inv0 = 1.0f / sF[384 + r0], inv1 = 1.0f / sF[384 + r1];
    const int n = b >> 3, hh = b & 7;
    const size_t base0 = ((size_t)(c * LCH + r0) * NB + n) * EMB + hh * HID;
    const size_t base1 = ((size_t)(c * LCH + r1) * NB + n) * EMB + hh * HID;
#pragma unroll
    for (int j = 0; j < 4; ++j) {
        int col = wn * 32 + j * 8 + gc;
        uint32_t hp, lp;
        split2(accO[j][0] * inv0, accO[j][1] * inv0, hp, lp);
        *reinterpret_cast<uint32_t*>(&g_attnH[base0 + col]) = hp;
        *reinterpret_cast<uint32_t*>(&g_attnL[base0 + col]) = lp;
        split2(accO[j][2] * inv1, accO[j][3] * inv1, hp, lp);
        *reinterpret_cast<uint32_t*>(&g_attnH[base1 + col]) = hp;
        *reinterpret_cast<uint32_t*>(&g_attnL[base1 + col]) = lp;
    }
}

// ---------------------------------------------------------------------------
// Kernel D v7: outproj cp.async pipeline (PDL wait at top)
// ---------------------------------------------------------------------------
#define ROWB2 144
#define BUF_BYTES (4 * 64 * ROWB2)
#define OAH2 0
#define OAL2 (64 * ROWB2)
#define OBH2 (2 * 64 * ROWB2)
#define OBL2 (3 * 64 * ROWB2)
#define SM_HMMA (2 * BUF_BYTES)

__global__ __launch_bounds__(256, 2) void outproj_hmma_kernel(const float* __restrict__ bias,
                                                              float* __restrict__ out) {
    extern __shared__ char smc[];
    const uint32_t sbase = smem_u32(smc);
    const int tid = threadIdx.x;
    const int wid = tid >> 5, lane = tid & 31;
    const int wm = wid & 3, wn = wid >> 2;
    const int rb = blockIdx.x * 64;
    const int nb = blockIdx.y * 64;

    PDL_WAIT();

    float acc[4][4];
#pragma unroll
    for (int nt = 0; nt < 4; ++nt)
#pragma unroll
        for (int e = 0; e < 4; ++e) acc[nt][e] = 0.f;

    auto stage = [&](int kc, int bufIdx) {
        const uint32_t bufs = sbase + bufIdx * BUF_BYTES;
        const size_t kbase = (size_t)kc * 64;
#pragma unroll
        for (int j = 0; j < 8; ++j) {
            int i = tid + j * 256;
            int arr = i >> 9;
            int jj = i & 511;
            int row = jj >> 3, g = jj & 7;
            const __nv_bfloat16* srcp;
            uint32_t dst;
            if (arr == 0) {
                srcp = &g_attnH[(size_t)(rb + row) * EMB + kbase + g * 8];
                dst = bufs + OAH2 + row * ROWB2 + g * 16;
            } else if (arr == 1) {
                srcp = &g_attnL[(size_t)(rb + row) * EMB + kbase + g * 8];
                dst = bufs + OAL2 + row * ROWB2 + g * 16;
            } else if (arr == 2) {
                srcp = &g_WH[(size_t)(nb + row) * EMB + kbase + g * 8];
                dst = bufs + OBH2 + row * ROWB2 + g * 16;
            } else {
                srcp = &g_WL[(size_t)(nb + row) * EMB + kbase + g * 8];
                dst = bufs + OBL2 + row * ROWB2 + g * 16;
            }
            cp16(dst, srcp);
        }
        CP_COMMIT();
    };

    const uint32_t aOff = (uint32_t)((wm * 16 + (lane & 15)) * ROWB2 + ((lane >> 4) * 8) * 2);
    const uint32_t bOff = (uint32_t)((wn * 32 + (lane & 7) + ((lane >> 4) << 3)) * ROWB2 +
                                     (((lane >> 3) & 1) * 8) * 2);

    stage(0, 0);
    for (int kc = 0; kc < 8; ++kc) {
        if (kc < 7) stage(kc + 1, (kc + 1) & 1);
        if (kc < 7) { CP_WAIT(1); } else { CP_WAIT(0); }
        __syncthreads();

        const uint32_t bufs = sbase + (kc & 1) * BUF_BYTES;
#pragma unroll
        for (int ks = 0; ks < 4; ++ks) {
            const int ko = ks * 32;
            uint32_t ah[4], al[4];
            ldsm_x4(ah[0], ah[1], ah[2], ah[3], bufs + OAH2 + aOff + ko);
            ldsm_x4(al[0], al[1], al[2], al[3], bufs + OAL2 + aOff + ko);
            uint32_t bh[4][2], bl[4][2];
#pragma unroll
            for (int p = 0; p < 2; ++p) {
                ldsm_x4(bh[2*p][0], bh[2*p][1], bh[2*p+1][0], bh[2*p+1][1],
                        bufs + OBH2 + bOff + p * 16 * ROWB2 + ko);
                ldsm_x4(bl[2*p][0], bl[2*p][1], bl[2*p+1][0], bl[2*p+1][1],
                        bufs + OBL2 + bOff + p * 16 * ROWB2 + ko);
            }
#pragma unroll
            for (int nt = 0; nt < 4; ++nt) {
                mma_bf16(acc[nt], ah, bh[nt]);
                mma_bf16(acc[nt], ah, bl[nt]);
                mma_bf16(acc[nt], al, bh[nt]);
            }
        }
        __syncthreads();
    }

    const int gr = lane >> 2, gc = (lane & 3) * 2;
    const int h = blockIdx.y;
#pragma unroll
    for (int nt = 0; nt < 4; ++nt) {
        int d = wn * 32 + nt * 8 + gc;
        float b0 = bias[nb + d], b1 = bias[nb + d + 1];
#pragma unroll
        for (int half = 0; half < 2; ++half) {
            int r = rb + wm * 16 + gr + half * 8;
            int t = r >> 1, n = r & 1;
            size_t oidx = (((size_t)(n * HH + h) * TT) + t) * HID + d;
            *reinterpret_cast<float2*>(out + oidx) =
                make_float2(acc[nt][half * 2 + 0] + b0,
                            acc[nt][half * 2 + 1] + b1);
        }
    }
}

// ---------------------------------------------------------------------------
// Launch: PDL-chained kernels via cudaLaunchKernelEx
// ---------------------------------------------------------------------------
template <typename F, typename... Args>
static inline void launch_pdl(F fn, dim3 grid, dim3 block, size_t smem, Args... args) {
    cudaLaunchConfig_t cfg = {};
    cfg.gridDim = grid;
    cfg.blockDim = block;
    cfg.dynamicSmemBytes = smem;
    cfg.stream = 0;
    cudaLaunchAttribute attr[1];
    attr[0].id = cudaLaunchAttributeProgrammaticStreamSerialization;
    attr[0].val.programmaticStreamSerializationAllowed = 1;
    cfg.attrs = attr;
    cfg.numAttrs = 1;
    cudaLaunchKernelEx(&cfg, fn, args...);
}

extern "C" void kernel_launch(void* const* d_in, const int* in_sizes, int n_in,
                              void* d_out, int out_size) {
    const float* q    = (const float*)d_in[0];
    const float* k    = (const float*)d_in[1];
    const float* v    = (const float*)d_in[2];
    const float* W    = (const float*)d_in[3];
    const float* bias = (const float*)d_in[4];
    float* out = (float*)d_out;

    static cudaStream_t s_side = nullptr;
    static cudaEvent_t evF = nullptr, evJ = nullptr;
    if (!s_side) {
        cudaStreamCreateWithFlags(&s_side, cudaStreamNonBlocking);
        cudaEventCreateWithFlags(&evF, cudaEventDisableTiming);
        cudaEventCreateWithFlags(&evJ, cudaEventDisableTiming);
    }

    cudaFuncSetAttribute(chunk_out_hmma,
                         cudaFuncAttributeMaxDynamicSharedMemorySize, SM_CO);
    cudaFuncSetAttribute(outproj_hmma_kernel,
                         cudaFuncAttributeMaxDynamicSharedMemorySize, SM_HMMA);

    const bool has_probs = (out_size > CTX_ELEMS);
    if (has_probs) {
        cudaEventRecord(evF, 0);
        cudaStreamWaitEvent(s_side, evF, 0);
        cudaMemsetAsync(out + CTX_ELEMS, 0,
                        (size_t)(out_size - CTX_ELEMS) * sizeof(float), s_side);
        cudaEventRecord(evJ, s_side);
    }

    chunk_sums_kernel<<<dim3(NHB, NCH + 4), 256, 33280>>>(k, v, W);
    launch_pdl(prefix_kernel, dim3(NHB, NCH), dim3(256), 0);
    launch_pdl(chunk_out_hmma, dim3(NHB, NCH), dim3(256), (size_t)SM_CO, q, k, v);
    launch_pdl(outproj_hmma_kernel, dim3(32, 8), dim3(256), (size_t)SM_HMMA, bias, out);

    if (has_probs) cudaStreamWaitEvent(0, evJ, 0);
}